// round 17
// baseline (speedup 1.0000x reference)
#include <cuda_runtime.h>
#include <cuda_bf16.h>
#include <cstdint>

#define VOCAB  50257
#define VPAD   50304          // 786 * 64
#define DMODEL 768
#define MTOT   4096           // B*S
#define SEQ    2048

#define BM 128
#define BN 64
#define BK 64
#define STAGES 3
#define NKC (DMODEL / BK)                  // 12
#define A_TILE_BYTES (BM * BK * 2)         // 16384
#define B_TILE_BYTES (BN * BK * 2)         // 8192
#define STAGE_BYTES (A_TILE_BYTES + B_TILE_BYTES)  // 24576
#define SMEM_BYTES (STAGES * STAGE_BYTES)  // 73728 -> 3 CTAs/SM

// prep: embed + bias only (W transpose folded into GEMM)
#define EM_BLOCKS MTOT                     // 4096
#define BI_BLOCKS ((VPAD + 255) / 256)     // 197
#define PREP_GRID (EM_BLOCKS + BI_BLOCKS)

// Scratch (static device globals — allocation-guard safe)
__device__ __nv_bfloat16 g_hid[(size_t)MTOT * DMODEL];  // hidden [m][k]
__device__ float         g_fb[VPAD];                    // float(bias), pad zeroed

// ---------------- helpers ----------------
__device__ __forceinline__ uint32_t smem_u32(const void* p) {
    return (uint32_t)__cvta_generic_to_shared(p);
}

__device__ __forceinline__ void ldsm4(uint32_t* r, uint32_t addr) {
    asm volatile("ldmatrix.sync.aligned.m8n8.x4.shared.b16 {%0,%1,%2,%3}, [%4];"
                 : "=r"(r[0]), "=r"(r[1]), "=r"(r[2]), "=r"(r[3]) : "r"(addr));
}

__device__ __forceinline__ void mma16816(float* c, const uint32_t* a, uint32_t b0, uint32_t b1) {
    asm volatile(
        "mma.sync.aligned.m16n8k16.row.col.f32.bf16.bf16.f32 "
        "{%0,%1,%2,%3}, {%4,%5,%6,%7}, {%8,%9}, {%0,%1,%2,%3};"
        : "+f"(c[0]), "+f"(c[1]), "+f"(c[2]), "+f"(c[3])
        : "r"(a[0]), "r"(a[1]), "r"(a[2]), "r"(a[3]), "r"(b0), "r"(b1));
}

__device__ __forceinline__ void cp16(uint32_t dst, const void* src) {
    asm volatile("cp.async.cg.shared.global [%0], [%1], 16;" :: "r"(dst), "l"(src));
}

__device__ __forceinline__ void sts128(uint32_t addr, uint32_t x, uint32_t y, uint32_t z, uint32_t u) {
    asm volatile("st.shared.v4.b32 [%0], {%1,%2,%3,%4};"
                 :: "r"(addr), "r"(x), "r"(y), "r"(z), "r"(u));
}

// ---------------- prep: embed gather + float bias (no W transpose anymore) ----------------
// wte/wpe arrive as int32 (harness widens int8 inputs), values in [-127,127].
__global__ void __launch_bounds__(256)
prep_kernel(const int* __restrict__ ids,
            const int* __restrict__ wte,
            const int* __restrict__ wpe,
            const int* __restrict__ bias) {
    const int b = blockIdx.x;
    const int t = threadIdx.x;

    if (b < EM_BLOCKS) {
        const int m = b;                   // 0..4095
        if (t < 192) {
            const int k4 = t * 4;
            const int id  = ids[m];
            const int pos = m & (SEQ - 1);
            int4 a = *(const int4*)(wte + (size_t)id  * DMODEL + k4);
            int4 p = *(const int4*)(wpe + (size_t)pos * DMODEL + k4);
            __nv_bfloat16 h[4];
            h[0] = __float2bfloat16((float)(a.x + p.x));
            h[1] = __float2bfloat16((float)(a.y + p.y));
            h[2] = __float2bfloat16((float)(a.z + p.z));
            h[3] = __float2bfloat16((float)(a.w + p.w));
            *(uint2*)(g_hid + (size_t)m * DMODEL + k4) = *(uint2*)h;
        }
    } else {
        const int i = (b - EM_BLOCKS) * 256 + t;
        if (i < VPAD) g_fb[i] = (i < VOCAB) ? (float)bias[i] : 0.f;
    }
}

// ---------------- main GEMM: 128x64 CTA, 4 warps of 64x32, 3 CTAs/SM ----------------
// A via cp.async (bf16 scratch); B loaded DIRECTLY from W int32 [k][v], converted
// int->bf16 in registers, STS'd into the same swizzled [v][k] smem layout as before.
__global__ void __launch_bounds__(128, 3)
gemm_kernel(const int* __restrict__ w, float* __restrict__ out) {
    extern __shared__ unsigned char smem[];
    const int tid  = threadIdx.x;
    const int wid  = tid >> 5;
    const int lane = tid & 31;
    const int m0 = blockIdx.x * BM;
    const int n0 = blockIdx.y * BN;
    const int wm = (wid & 1) * 64;   // 2 warps in m
    const int wn = (wid >> 1) * 32;  // 2 warps in n

    const uint32_t sbase = smem_u32(smem);
    const __nv_bfloat16* gA = g_hid + (size_t)m0 * DMODEL;

    // A-tile cp.async coords: 1024 chunks / 128 threads = 8 each
    int lcoA[8];
    const __nv_bfloat16* lsa[8];
    #pragma unroll
    for (int i = 0; i < 8; i++) {
        int idx = tid + i * 128;
        int r = idx >> 3, c = idx & 7;
        lcoA[i] = r * 128 + ((c ^ (r & 7)) << 4);
        lsa[i]  = gA + (size_t)r * DMODEL + c * 8;
    }

    // B direct-load assignment: thread covers v = tid&63 (1 row), k-half = (tid>>6)*32
    const int bv  = tid & 63;
    const int bk0 = (tid >> 6) * 32;       // 0 or 32
    const bool vok = (n0 + bv) < VOCAB;
    const int* wp = w + (n0 + bv);         // column base; row k at + (size_t)k*VOCAB
    // swizzled STS row base (stage-relative): row bv, chunks c = bk0/8 + q
    const uint32_t brow = (uint32_t)(bv * 128);

    float acc[4][4][4];
    #pragma unroll
    for (int f = 0; f < 4; f++)
        #pragma unroll
        for (int j = 0; j < 4; j++)
            #pragma unroll
            for (int q = 0; q < 4; q++) acc[f][j][q] = 0.f;

    // ---- B stage fill: LDG(32 int) -> cvt bf16 -> 4x STS.128 into stage st ----
    auto fill_b = [&](int kcs, int st) {
        int bw[32];
        #pragma unroll
        for (int j = 0; j < 32; j++)
            bw[j] = vok ? wp[(size_t)(kcs * BK + bk0 + j) * VOCAB] : 0;
        uint32_t base = sbase + st * STAGE_BYTES + A_TILE_BYTES;
        #pragma unroll
        for (int q = 0; q < 4; q++) {
            uint32_t pk[4];
            #pragma unroll
            for (int p = 0; p < 4; p++) {
                __nv_bfloat162 h2 = __floats2bfloat162_rn(
                    (float)bw[q * 8 + p * 2], (float)bw[q * 8 + p * 2 + 1]);
                pk[p] = *(uint32_t*)&h2;
            }
            const int c = (bk0 >> 3) + q;   // 16B chunk index 0..7
            sts128(base + brow + (uint32_t)(((c ^ (bv & 7)) << 4)), pk[0], pk[1], pk[2], pk[3]);
        }
    };

    // ---- prologue: stages 0..STAGES-2 ----
    #pragma unroll
    for (int s = 0; s < STAGES - 1; s++) {
        uint32_t dstA = sbase + s * STAGE_BYTES;
        #pragma unroll
        for (int i = 0; i < 8; i++) cp16(dstA + lcoA[i], lsa[i] + s * BK);
        asm volatile("cp.async.commit_group;");
        fill_b(s, s);
    }

    const int lrow = lane & 15;
    const int lhi  = lane >> 4;

    #pragma unroll 3
    for (int kc = 0; kc < NKC; kc++) {
        asm volatile("cp.async.wait_group %0;" :: "n"(STAGES - 2));
        __syncthreads();

        const int st = kc % STAGES;
        const uint32_t baseA = sbase + st * STAGE_BYTES;
        const uint32_t baseB = baseA + A_TILE_BYTES;

        const int nk = kc + STAGES - 1;
        const int st2 = nk % STAGES;
        // issue next-stage A loads + B LDGs early (latency hidden under HMMA)
        int bw[32];
        if (nk < NKC) {
            uint32_t dstA = sbase + st2 * STAGE_BYTES;
            #pragma unroll
            for (int i = 0; i < 8; i++) cp16(dstA + lcoA[i], lsa[i] + nk * BK);
            #pragma unroll
            for (int j = 0; j < 32; j++)
                bw[j] = vok ? wp[(size_t)(nk * BK + bk0 + j) * VOCAB] : 0;
        }
        asm volatile("cp.async.commit_group;");

        #pragma unroll
        for (int kk = 0; kk < 4; kk++) {
            const int c = kk * 2 + lhi;
            uint32_t a[4][4], b[2][4];
            #pragma unroll
            for (int f = 0; f < 4; f++) {
                int r = wm + f * 16 + lrow;
                ldsm4(a[f], baseA + r * 128 + ((c ^ (r & 7)) << 4));
            }
            #pragma unroll
            for (int g = 0; g < 2; g++) {
                int r = wn + g * 16 + lrow;
                ldsm4(b[g], baseB + r * 128 + ((c ^ (r & 7)) << 4));
            }
            #pragma unroll
            for (int f = 0; f < 4; f++)
                #pragma unroll
                for (int g = 0; g < 2; g++) {
                    mma16816(acc[f][2 * g + 0], a[f], b[g][0], b[g][2]);
                    mma16816(acc[f][2 * g + 1], a[f], b[g][1], b[g][3]);
                }
        }

        // convert + STS the prefetched B regs into stage st2 (consumed at kc+2)
        if (nk < NKC) {
            uint32_t base = sbase + st2 * STAGE_BYTES + A_TILE_BYTES;
            #pragma unroll
            for (int q = 0; q < 4; q++) {
                uint32_t pk[4];
                #pragma unroll
                for (int p = 0; p < 4; p++) {
                    __nv_bfloat162 h2 = __floats2bfloat162_rn(
                        (float)bw[q * 8 + p * 2], (float)bw[q * 8 + p * 2 + 1]);
                    pk[p] = *(uint32_t*)&h2;
                }
                const int c = (bk0 >> 3) + q;
                sts128(base + brow + (uint32_t)(((c ^ (bv & 7)) << 4)), pk[0], pk[1], pk[2], pk[3]);
            }
        }
    }

    // ---- epilogue: out = acc + float(bias); scalar 4B stores (VOCAB odd) ----
    float fb0[4], fb1[4];
    #pragma unroll
    for (int j = 0; j < 4; j++) {
        const int col = n0 + wn + j * 8 + ((lane & 3) << 1);
        fb0[j] = g_fb[col];
        fb1[j] = g_fb[col + 1 < VPAD ? col + 1 : col];
    }
    #pragma unroll
    for (int f = 0; f < 4; f++) {
        const int r = m0 + wm + f * 16 + (lane >> 2);
        float* row0 = out + (size_t)r * VOCAB;
        float* row1 = row0 + (size_t)8 * VOCAB;
        #pragma unroll
        for (int j = 0; j < 4; j++) {
            const int col = n0 + wn + j * 8 + ((lane & 3) << 1);
            if (col < VOCAB) {
                row0[col] = acc[f][j][0] + fb0[j];
                row1[col] = acc[f][j][2] + fb0[j];
            }
            if (col + 1 < VOCAB) {
                row0[col + 1] = acc[f][j][1] + fb1[j];
                row1[col + 1] = acc[f][j][3] + fb1[j];
            }
        }
    }
}

// ---------------- launch ----------------
extern "C" void kernel_launch(void* const* d_in, const int* in_sizes, int n_in,
                              void* d_out, int out_size) {
    const int* ids  = (const int*)d_in[0];   // [2,2048] int32
    const int* wte  = (const int*)d_in[1];   // [50257,768] int8 widened to int32
    const int* wpe  = (const int*)d_in[2];   // [2048,768] int8 widened to int32
    const int* w    = (const int*)d_in[3];   // [768,50257] int32
    const int* bias = (const int*)d_in[4];   // [50257] int32
    float* out = (float*)d_out;              // [2,2048,50257] float32

    cudaFuncSetAttribute(gemm_kernel, cudaFuncAttributeMaxDynamicSharedMemorySize, SMEM_BYTES);

    prep_kernel<<<PREP_GRID, 256>>>(ids, wte, wpe, bias);
    gemm_kernel<<<dim3(MTOT / BM, VPAD / BN), 128, SMEM_BYTES>>>(w, out);
}